// round 1
// baseline (speedup 1.0000x reference)
#include <cuda_runtime.h>
#include <cuda_bf16.h>
#include <math.h>

// ---------------------------------------------------------------------------
// Problem constants
// ---------------------------------------------------------------------------
#define B_   16
#define N_   3136          // 56*56
#define DIM  512
#define HEADS 8
#define WS   7
#define HW   56
#define SD   256           // DIM/2
#define S_   32            // SD/HEADS
#define BN   (B_ * N_)     // 50176 rows
#define ELEMS ((long)BN * DIM)   // 25,690,112

// Scratch (static __device__ arrays; cudaMalloc is forbidden)
__device__ float g_buf1[ELEMS];   // dwconv out, then q
__device__ float g_buf2[ELEMS];   // kv (pwconv out)
__device__ float g_buf3[ELEMS];   // attention output (pre-proj)
__device__ float g_k[2 * B_ * HEADS * 49 * S_];   // pre-scaled by 1/sqrt(32)
__device__ float g_v[2 * B_ * HEADS * 49 * S_];

// ---------------------------------------------------------------------------
// 3x3 depthwise conv, pad 1, layout (B, N=H*W, C) channel-contiguous
// ---------------------------------------------------------------------------
__global__ void dwconv_kernel(const float* __restrict__ x,
                              const float* __restrict__ w,
                              const float* __restrict__ bias,
                              float* __restrict__ out) {
    int p = blockIdx.x;               // 0..BN-1
    int b = p / N_;
    int pix = p - b * N_;
    int hy = pix / HW, hx = pix - hy * HW;
    int c = threadIdx.x;              // 512 threads
    float acc = bias[c];
    #pragma unroll
    for (int dy = 0; dy < 3; dy++) {
        int yy = hy + dy - 1;
        if (yy < 0 || yy >= HW) continue;
        #pragma unroll
        for (int dx = 0; dx < 3; dx++) {
            int xx = hx + dx - 1;
            if (xx < 0 || xx >= HW) continue;
            acc += w[c * 9 + dy * 3 + dx] *
                   x[((long)b * N_ + yy * HW + xx) * DIM + c];
        }
    }
    out[(long)p * DIM + c] = acc;
}

// ---------------------------------------------------------------------------
// SGEMM: C[M,512] = A[M,512] @ W[512,512]^T (+ bias)
// 64x64 tile, 256 threads, 4x4 microtile, K-tile 16
// ---------------------------------------------------------------------------
__global__ void gemm64_kernel(const float* __restrict__ A,
                              const float* __restrict__ W,
                              const float* __restrict__ bias,
                              float* __restrict__ C) {
    const int K = DIM, N = DIM;
    __shared__ float As[16][68];
    __shared__ float Bs[16][68];
    int tid = threadIdx.x;
    int tx = tid & 15, ty = tid >> 4;
    long m0 = (long)blockIdx.x * 64;
    int n0 = blockIdx.y * 64;
    int lrow = tid >> 2;            // 0..63
    int lseg = (tid & 3) << 2;      // 0,4,8,12
    float acc[4][4] = {};

    const float* Ap = A + (m0 + lrow) * K + lseg;
    const float* Wp = W + (long)(n0 + lrow) * K + lseg;

    for (int k0 = 0; k0 < K; k0 += 16) {
        float4 av = *(const float4*)(Ap + k0);
        float4 bv = *(const float4*)(Wp + k0);
        As[lseg + 0][lrow] = av.x; As[lseg + 1][lrow] = av.y;
        As[lseg + 2][lrow] = av.z; As[lseg + 3][lrow] = av.w;
        Bs[lseg + 0][lrow] = bv.x; Bs[lseg + 1][lrow] = bv.y;
        Bs[lseg + 2][lrow] = bv.z; Bs[lseg + 3][lrow] = bv.w;
        __syncthreads();
        #pragma unroll
        for (int kk = 0; kk < 16; kk++) {
            float4 a = *(const float4*)&As[kk][ty << 2];
            float4 bq = *(const float4*)&Bs[kk][tx << 2];
            acc[0][0] += a.x * bq.x; acc[0][1] += a.x * bq.y;
            acc[0][2] += a.x * bq.z; acc[0][3] += a.x * bq.w;
            acc[1][0] += a.y * bq.x; acc[1][1] += a.y * bq.y;
            acc[1][2] += a.y * bq.z; acc[1][3] += a.y * bq.w;
            acc[2][0] += a.z * bq.x; acc[2][1] += a.z * bq.y;
            acc[2][2] += a.z * bq.z; acc[2][3] += a.z * bq.w;
            acc[3][0] += a.w * bq.x; acc[3][1] += a.w * bq.y;
            acc[3][2] += a.w * bq.z; acc[3][3] += a.w * bq.w;
        }
        __syncthreads();
    }
    #pragma unroll
    for (int ii = 0; ii < 4; ii++) {
        long mm = m0 + (ty << 2) + ii;
        #pragma unroll
        for (int jj = 0; jj < 4; jj++) {
            int nn = n0 + (tx << 2) + jj;
            float v = acc[ii][jj];
            if (bias) v += bias[nn];
            C[mm * N + nn] = v;
        }
    }
}

// ---------------------------------------------------------------------------
// Per (branch, b, head): unfold -> pooled -> fc -> single -> k/v, v += local dwconv
// ---------------------------------------------------------------------------
__global__ void prep_kernel(const float* __restrict__ kv,
                            const float* __restrict__ fc0, const float* __restrict__ fc1,
                            const float* __restrict__ sg0, const float* __restrict__ sg1,
                            const float* __restrict__ lw0, const float* __restrict__ lb0,
                            const float* __restrict__ lw1, const float* __restrict__ lb1) {
    int blk = blockIdx.x;       // 0..255 : (branch, b, h)
    int br = blk >> 7;
    int bh = blk & 127;
    int b = bh >> 3, h = bh & 7;
    int tid = threadIdx.x;      // 256

    __shared__ float pooled[49][32];
    __shared__ float tmp[49][32];
    __shared__ float vsh[49][33];

    int chbase = br * SD + h * S_;

    // pooled[w][s]
    for (int idx = tid; idx < 49 * 32; idx += 256) {
        int w = idx >> 5, s = idx & 31;
        int ky = w / 7, kx = w - ky * 7;
        float sum = 0.f;
        if (br == 0) {
            // LL=64, stride 7, dil 1: mean over windows {2s,2s+1}, all 32 ch
            #pragma unroll
            for (int t = 0; t < 2; t++) {
                int ll = 2 * s + t;
                int ly = ll >> 3, lx = ll & 7;
                int py = ly * 7 + ky, px = lx * 7 + kx;
                const float* src = kv + ((long)b * N_ + py * HW + px) * DIM + chbase;
                #pragma unroll
                for (int c = 0; c < 32; c++) sum += src[c];
            }
            sum *= (1.f / 64.f);
        } else {
            // LL=16, stride 13, dil 2: window s/2, channels 16*(s&1)..+16
            int ll = s >> 1;
            int ly = ll >> 2, lx = ll & 3;
            int py = ly * 13 + ky * 2, px = lx * 13 + kx * 2;
            const float* src = kv + ((long)b * N_ + py * HW + px) * DIM
                               + chbase + 16 * (s & 1);
            #pragma unroll
            for (int c = 0; c < 16; c++) sum += src[c];
            sum *= (1.f / 16.f);
        }
        pooled[w][s] = sum;
    }
    __syncthreads();

    // tmp = pooled @ fc^T
    const float* fc = br ? fc1 : fc0;
    for (int idx = tid; idx < 49 * 32; idx += 256) {
        int w = idx >> 5, t = idx & 31;
        float sum = 0.f;
        #pragma unroll
        for (int s = 0; s < 32; s++) sum += pooled[w][s] * fc[t * 32 + s];
        tmp[w][t] = sum;
    }
    __syncthreads();

    // kvp = tmp @ single^T ; j<32 -> k (scaled), j>=32 -> v
    const float* sg = br ? sg1 : sg0;
    const float kscale = 0.17677669529663689f;  // 1/sqrt(32)
    for (int idx = tid; idx < 49 * 64; idx += 256) {
        int w = idx >> 6, j = idx & 63;
        float sum = 0.f;
        #pragma unroll
        for (int t = 0; t < 32; t++) sum += tmp[w][t] * sg[j * 32 + t];
        if (j < 32)
            g_k[(long)blk * 49 * 32 + w * 32 + j] = sum * kscale;
        else
            vsh[w][j - 32] = sum;
    }
    __syncthreads();

    // v += 3x3 depthwise conv over the 7x7 window grid (+bias)
    const float* lw = br ? lw1 : lw0;
    const float* lb = br ? lb1 : lb0;
    for (int idx = tid; idx < 49 * 32; idx += 256) {
        int w = idx >> 5, s = idx & 31;
        int wy = w / 7, wx = w - wy * 7;
        int ch = h * S_ + s;
        float acc = vsh[w][s] + lb[ch];
        #pragma unroll
        for (int dy = 0; dy < 3; dy++) {
            int yy = wy + dy - 1;
            if (yy < 0 || yy >= 7) continue;
            #pragma unroll
            for (int dx = 0; dx < 3; dx++) {
                int xx = wx + dx - 1;
                if (xx < 0 || xx >= 7) continue;
                acc += lw[ch * 9 + dy * 3 + dx] * vsh[yy * 7 + xx][s];
            }
        }
        g_v[(long)blk * 49 * 32 + w * 32 + s] = acc;
    }
}

// ---------------------------------------------------------------------------
// Attention: per (branch,b,h) block-column, thread-per-query, 49 keys in smem
// ---------------------------------------------------------------------------
__global__ void attn_kernel(const float* __restrict__ q,
                            float* __restrict__ att) {
    int blk = blockIdx.x;       // (branch, b, h)
    int br = blk >> 7;
    int bh = blk & 127;
    int b = bh >> 3, h = bh & 7;
    int tid = threadIdx.x;      // 256

    __shared__ float ksh[49][32];
    __shared__ float vsh[49][32];
    __shared__ float osh[256][33];

    const float* kp = g_k + (long)blk * 1568;
    const float* vp = g_v + (long)blk * 1568;
    for (int idx = tid; idx < 1568; idx += 256) {
        ((float*)ksh)[idx] = kp[idx];
        ((float*)vsh)[idx] = vp[idx];
    }
    __syncthreads();

    int n0 = blockIdx.y * 256;
    int n = n0 + tid;
    float p[49];
    if (n < N_) {
        const float* qp = q + ((long)b * N_ + n) * DIM + h * 64 + br * 32;
        float4 qv4[8];
        #pragma unroll
        for (int v = 0; v < 8; v++) qv4[v] = *(const float4*)(qp + v * 4);
        float qv[32];
        #pragma unroll
        for (int v = 0; v < 8; v++) {
            qv[v * 4 + 0] = qv4[v].x; qv[v * 4 + 1] = qv4[v].y;
            qv[v * 4 + 2] = qv4[v].z; qv[v * 4 + 3] = qv4[v].w;
        }
        float m = -1e30f;
        #pragma unroll
        for (int j = 0; j < 49; j++) {
            float s = 0.f;
            #pragma unroll
            for (int d = 0; d < 32; d++) s += qv[d] * ksh[j][d];
            p[j] = s;
            m = fmaxf(m, s);
        }
        float sum = 0.f;
        #pragma unroll
        for (int j = 0; j < 49; j++) { p[j] = __expf(p[j] - m); sum += p[j]; }
        float inv = 1.f / sum;
        #pragma unroll
        for (int d = 0; d < 32; d++) {
            float acc = 0.f;
            #pragma unroll
            for (int j = 0; j < 49; j++) acc += p[j] * vsh[j][d];
            osh[tid][d] = acc * inv;
        }
    }
    __syncthreads();

    // coalesced write: channel = br*256 + h*32 + d
    int off = br * SD + h * S_;
    for (int idx = tid; idx < 256 * 32; idx += 256) {
        int qq = idx >> 5, d = idx & 31;
        int nn = n0 + qq;
        if (nn < N_) att[((long)b * N_ + nn) * DIM + off + d] = osh[qq][d];
    }
}

// ---------------------------------------------------------------------------
// Launch
// ---------------------------------------------------------------------------
extern "C" void kernel_launch(void* const* d_in, const int* in_sizes, int n_in,
                              void* d_out, int out_size) {
    const float* x        = (const float*)d_in[0];
    // d_in[1], d_in[2] are H, W scalars (56) — hardcoded
    const float* q_w      = (const float*)d_in[3];
    const float* kv_dw_w  = (const float*)d_in[4];
    const float* kv_dw_b  = (const float*)d_in[5];
    const float* kv_pw_w  = (const float*)d_in[6];
    const float* kv_pw_b  = (const float*)d_in[7];
    const float* fc_w0    = (const float*)d_in[8];
    const float* fc_w1    = (const float*)d_in[9];
    const float* sg_w0    = (const float*)d_in[10];
    const float* sg_w1    = (const float*)d_in[11];
    const float* lw0      = (const float*)d_in[12];
    const float* lb0      = (const float*)d_in[13];
    const float* lw1      = (const float*)d_in[14];
    const float* lb1      = (const float*)d_in[15];
    const float* proj_w   = (const float*)d_in[16];
    const float* proj_b   = (const float*)d_in[17];
    float* out = (float*)d_out;

    float *buf1, *buf2, *buf3;
    cudaGetSymbolAddress((void**)&buf1, g_buf1);
    cudaGetSymbolAddress((void**)&buf2, g_buf2);
    cudaGetSymbolAddress((void**)&buf3, g_buf3);

    dim3 ggrid(BN / 64, DIM / 64);   // 784 x 8

    // 1) depthwise conv on x -> buf1
    dwconv_kernel<<<BN, DIM>>>(x, kv_dw_w, kv_dw_b, buf1);
    // 2) pointwise conv: kv = buf1 @ pw^T + b -> buf2
    gemm64_kernel<<<ggrid, 256>>>(buf1, kv_pw_w, kv_pw_b, buf2);
    // 3) q = x @ q_w^T -> buf1 (dw output no longer needed)
    gemm64_kernel<<<ggrid, 256>>>(x, q_w, nullptr, buf1);
    // 4) branch prep (pool/fc/single/local dwconv) -> g_k, g_v
    prep_kernel<<<256, 256>>>(buf2, fc_w0, fc_w1, sg_w0, sg_w1,
                              lw0, lb0, lw1, lb1);
    // 5) attention -> buf3
    attn_kernel<<<dim3(256, (N_ + 255) / 256), 256>>>(buf1, buf3);
    // 6) out = buf3 @ proj^T + bias
    gemm64_kernel<<<ggrid, 256>>>(buf3, proj_w, proj_b, out);
}